// round 13
// baseline (speedup 1.0000x reference)
#include <cuda_runtime.h>
#include <cuda_fp16.h>
#include <cuda_bf16.h>
#include <cstdint>

// ---------------- problem constants ----------------
#define L_SEQ 512
#define B_N   256
#define E_DIM 128
#define H_DIM 128
#define G4    512     // 4*H
#define T_TAG 48
#define NB    4       // batch lanes per LSTM CTA (half of mma N=8 tile)

typedef unsigned long long ull;

// ---------------- scratch (device globals; no allocation allowed) ----------------
__device__ __nv_bfloat16 g_xproj_f[(size_t)L_SEQ * B_N * G4];   // 128 MiB
__device__ __nv_bfloat16 g_xproj_b[(size_t)L_SEQ * B_N * G4];   // 128 MiB
__device__ __nv_bfloat16 g_hcat[(size_t)L_SEQ * B_N * 256];     // 64 MiB [l][b][2H]
__device__ float g_emis[(size_t)L_SEQ * B_N * T_TAG];           // 24 MiB
__device__ float g_llh[B_N];
__device__ int   g_crf_ctr;                                     // zero-init; reset each run

// ---------------- generic helpers ----------------
__device__ __forceinline__ float tanh_fast(float x) {
    float y;
    asm("tanh.approx.f32 %0, %1;" : "=f"(y) : "f"(x));
    return y;
}
__device__ __forceinline__ float sig_fast(float x) {
    return fmaf(0.5f, tanh_fast(0.5f * x), 0.5f);
}
__device__ __forceinline__ uint32_t smem_u32(const void* p) {
    uint32_t a;
    asm("{ .reg .u64 t; cvta.to.shared.u64 t, %1; cvt.u32.u64 %0, t; }" : "=r"(a) : "l"(p));
    return a;
}
__device__ __forceinline__ uint32_t bf2(float x, float y) {
    __nv_bfloat162 t = __floats2bfloat162_rn(x, y);
    return *(uint32_t*)&t;
}
__device__ __forceinline__ void ffma2(ull& d, ull a, ull b) {
    asm("fma.rn.f32x2 %0, %1, %2, %0;" : "+l"(d) : "l"(a), "l"(b));
}
__device__ __forceinline__ float2 unpack2(ull v) {
    float2 r;
    asm("mov.b64 {%0, %1}, %2;" : "=f"(r.x), "=f"(r.y) : "l"(v));
    return r;
}
__device__ __forceinline__ void mma_bf16(float* d, const uint32_t* a, const uint32_t* b) {
    asm volatile(
        "mma.sync.aligned.m16n8k16.row.col.f32.bf16.bf16.f32 "
        "{%0,%1,%2,%3}, {%4,%5,%6,%7}, {%8,%9}, {%0,%1,%2,%3};"
        : "+f"(d[0]), "+f"(d[1]), "+f"(d[2]), "+f"(d[3])
        : "r"(a[0]), "r"(a[1]), "r"(a[2]), "r"(a[3]), "r"(b[0]), "r"(b[1]));
}
__device__ __forceinline__ void ldmatrix_x2_trans(uint32_t* r, uint32_t addr) {
    asm volatile("ldmatrix.sync.aligned.m8n8.x2.trans.shared.b16 {%0,%1}, [%2];"
                 : "=r"(r[0]), "=r"(r[1]) : "r"(addr));
}
__device__ __forceinline__ void ldsm_x4(uint32_t* r, uint32_t a) {
    asm volatile("ldmatrix.sync.aligned.m8n8.x4.shared.b16 {%0,%1,%2,%3}, [%4];"
                 : "=r"(r[0]), "=r"(r[1]), "=r"(r[2]), "=r"(r[3]) : "r"(a));
}
__device__ __forceinline__ void ldsm_x2(uint32_t* r, uint32_t a) {
    asm volatile("ldmatrix.sync.aligned.m8n8.x2.shared.b16 {%0,%1}, [%2];"
                 : "=r"(r[0]), "=r"(r[1]) : "r"(a));
}
__device__ __forceinline__ void cp16(uint32_t dst, const void* src) {
    asm volatile("cp.async.ca.shared.global [%0], [%1], 16;" :: "r"(dst), "l"(src));
}
__device__ __forceinline__ float warp_sum(float v) {
#pragma unroll
    for (int o = 16; o; o >>= 1) v += __shfl_xor_sync(0xFFFFFFFFu, v, o);
    return v;
}
__device__ __forceinline__ int warp_sum_i(int v) {
#pragma unroll
    for (int o = 16; o; o >>= 1) v += __shfl_xor_sync(0xFFFFFFFFu, v, o);
    return v;
}

// ============================================================================
// Kernel 1: xproj = emb[words] @ Wih^T + (bih+bhh) via HMMA bf16, bf16 output.
// CTA tile: 128 rows x 128 gates, K=128. (unchanged)
// ============================================================================
#define XPM_A_OFF    0
#define XPM_B_OFF    (128 * 136 * 2)
#define XPM_BIAS_OFF (2 * 128 * 136 * 2)
#define XPM_SMEM     (XPM_BIAS_OFF + 128 * 4)

__global__ __launch_bounds__(256) void xproj_mma_kernel(
    const int* __restrict__ words, const float* __restrict__ emb,
    const float* __restrict__ Wih_f, const float* __restrict__ bih_f,
    const float* __restrict__ bhh_f, const float* __restrict__ Wih_b,
    const float* __restrict__ bih_b, const float* __restrict__ bhh_b) {
    extern __shared__ char xsm[];
    __nv_bfloat16* A_s = (__nv_bfloat16*)(xsm + XPM_A_OFF);   // [128][136]
    __nv_bfloat16* B_s = (__nv_bfloat16*)(xsm + XPM_B_OFF);   // [128][136]
    float* bias_s      = (float*)(xsm + XPM_BIAS_OFF);        // [128]

    const int dir = blockIdx.z;
    const float* Wih = dir ? Wih_b : Wih_f;
    const float* b1  = dir ? bih_b : bih_f;
    const float* b2  = dir ? bhh_b : bhh_f;
    __nv_bfloat16* out = dir ? g_xproj_b : g_xproj_f;

    const int row0 = blockIdx.y * 128;
    const int n0   = blockIdx.x * 128;
    const int tid  = threadIdx.x;

    if (tid < 128) bias_s[tid] = b1[n0 + tid] + b2[n0 + tid];

    {
        const int r = tid >> 1, hf = tid & 1;
        const int grow = row0 + r;
        const int l = grow >> 8, b = grow & 255;
        const int w = words[b * L_SEQ + l];
        const float4* src = (const float4*)(emb + (size_t)w * E_DIM + hf * 64);
        __nv_bfloat16* dst = A_s + r * 136 + hf * 64;
#pragma unroll
        for (int i = 0; i < 8; ++i) {
            float4 v0 = src[2 * i], v1 = src[2 * i + 1];
            uint4 pk;
            pk.x = bf2(v0.x, v0.y);
            pk.y = bf2(v0.z, v0.w);
            pk.z = bf2(v1.x, v1.y);
            pk.w = bf2(v1.z, v1.w);
            *(uint4*)(dst + i * 8) = pk;
        }
    }
    {
        const int r = tid >> 1, hf = tid & 1;
        const float4* src = (const float4*)(Wih + (size_t)(n0 + r) * E_DIM + hf * 64);
        __nv_bfloat16* dst = B_s + r * 136 + hf * 64;
#pragma unroll
        for (int i = 0; i < 8; ++i) {
            float4 v0 = src[2 * i], v1 = src[2 * i + 1];
            uint4 pk;
            pk.x = bf2(v0.x, v0.y);
            pk.y = bf2(v0.z, v0.w);
            pk.z = bf2(v1.x, v1.y);
            pk.w = bf2(v1.z, v1.w);
            *(uint4*)(dst + i * 8) = pk;
        }
    }
    __syncthreads();

    const uint32_t As = smem_u32(A_s), Bs = smem_u32(B_s);
    const int lane = tid & 31, wid = tid >> 5;
    const int m_base = (wid >> 1) * 32;
    const int n_base = (wid & 1) * 64;

    float d[2][8][4];
#pragma unroll
    for (int mt = 0; mt < 2; ++mt)
#pragma unroll
        for (int nt = 0; nt < 8; ++nt)
#pragma unroll
            for (int c = 0; c < 4; ++c) d[mt][nt][c] = 0.f;

    const int aq = lane >> 3;
    const uint32_t a_row = (uint32_t)((aq & 1) * 8 + (lane & 7));
    const uint32_t a_col = (uint32_t)((aq >> 1) * 16);
    const uint32_t b_row = (uint32_t)(lane & 7);
    const uint32_t b_col = (uint32_t)(((lane >> 3) & 1) * 16);

#pragma unroll
    for (int ks = 0; ks < 8; ++ks) {
        uint32_t a0[4], a1[4];
        ldsm_x4(a0, As + (m_base + 0 + a_row) * 272 + ks * 32 + a_col);
        ldsm_x4(a1, As + (m_base + 16 + a_row) * 272 + ks * 32 + a_col);
#pragma unroll
        for (int nt = 0; nt < 8; ++nt) {
            uint32_t bb[2];
            ldsm_x2(bb, Bs + (n_base + nt * 8 + b_row) * 272 + ks * 32 + b_col);
            mma_bf16(d[0][nt], a0, bb);
            mma_bf16(d[1][nt], a1, bb);
        }
    }

    const int r = lane >> 2, c = (lane & 3) * 2;
#pragma unroll
    for (int mt = 0; mt < 2; ++mt) {
        const int gr = row0 + m_base + mt * 16 + r;
#pragma unroll
        for (int nt = 0; nt < 8; ++nt) {
            const int gc = n_base + nt * 8 + c;
            const float bx = bias_s[gc], by = bias_s[gc + 1];
            *(uint32_t*)(out + (size_t)gr * G4 + n0 + gc) =
                bf2(d[mt][nt][0] + bx, d[mt][nt][1] + by);
            *(uint32_t*)(out + (size_t)(gr + 8) * G4 + n0 + gc) =
                bf2(d[mt][nt][2] + bx, d[mt][nt][3] + by);
        }
    }
}

// ============================================================================
// Kernel 2: HMMA LSTM. 256 threads, NB=4 batch/CTA (128 CTAs -> 1/SM).
// MMA accumulators initialized directly from x (loop-top LDS, latency hidden)
// — no post-MMA x adds on the critical path.
// ============================================================================
#define LSTM_HBUF   0
#define LSTM_XBUF   4096
#define XB_STRIDE   520                       // bf16 units per batch row
#define XB_BUFSZ    (4 * XB_STRIDE)           // bf16 units per buffer
#define LSTM_SMEM   (4096 + 4 * XB_BUFSZ * 2)

__global__ __launch_bounds__(256) void lstm_mma_kernel(const float* __restrict__ Whh_f,
                                                       const float* __restrict__ Whh_b) {
    extern __shared__ char smraw[];
    uint32_t* hbuf      = (uint32_t*)(smraw + LSTM_HBUF);       // [2][128][4 bf16x2]
    __nv_bfloat16* xbuf = (__nv_bfloat16*)(smraw + LSTM_XBUF);  // [4][4][520]

    const int tid  = threadIdx.x;
    const int lane = tid & 31;
    const int wid  = tid >> 5;
    const int gid  = lane >> 2;
    const int tig  = lane & 3;
    const int dir  = blockIdx.y;
    const int b0   = blockIdx.x * NB;
    const float* Whh = dir ? Whh_b : Whh_f;
    const __nv_bfloat16* xp = dir ? g_xproj_b : g_xproj_f;
    __nv_bfloat16* hout     = g_hcat + dir * 128;

    const uint32_t hb_u32 = smem_u32(hbuf);
    const uint32_t xb_u32 = smem_u32(xbuf);
    const bool live = (tig < 2);   // batches 2*tig, 2*tig+1 in [0,4)

    uint32_t afr[4][8][4];
#pragma unroll
    for (int q = 0; q < 4; ++q) {
        const int r0 = 16 * wid + 128 * q + gid;
#pragma unroll
        for (int ks = 0; ks < 8; ++ks) {
            const int cc = ks * 16 + 2 * tig;
            float2 v00 = *(const float2*)(Whh + (size_t)r0 * 128 + cc);
            float2 v10 = *(const float2*)(Whh + (size_t)(r0 + 8) * 128 + cc);
            float2 v01 = *(const float2*)(Whh + (size_t)r0 * 128 + cc + 8);
            float2 v11 = *(const float2*)(Whh + (size_t)(r0 + 8) * 128 + cc + 8);
            afr[q][ks][0] = bf2(v00.x, v00.y);
            afr[q][ks][1] = bf2(v10.x, v10.y);
            afr[q][ks][2] = bf2(v01.x, v01.y);
            afr[q][ks][3] = bf2(v11.x, v11.y);
        }
    }

    for (int i = tid; i < 2 * 128 * 4; i += 256) hbuf[i] = 0;

    // prologue: prefetch x(0..2) — 256 x 16B per buffer (1 cp16/thread)
#pragma unroll
    for (int ps = 0; ps < 3; ++ps) {
        const int l = dir ? (L_SEQ - 1 - ps) : ps;
        const __nv_bfloat16* src = xp + ((size_t)l * B_N + b0) * G4;
        const int brow = tid >> 6, c16 = tid & 63;
        cp16(xb_u32 + (uint32_t)(ps * XB_BUFSZ * 2 + brow * XB_STRIDE * 2 + c16 * 16),
             src + brow * 512 + c16 * 8);
        asm volatile("cp.async.commit_group;");
    }
    asm volatile("cp.async.wait_group 2;");   // x(0) ready
    __syncthreads();

    float cst[4] = {0.f, 0.f, 0.f, 0.f};

    for (int s = 0; s < L_SEQ; ++s) {
        const int l = dir ? (L_SEQ - 1 - s) : s;

        // issue prefetch x(s+3) (group always committed to keep the count)
        if (s + 3 < L_SEQ) {
            const int lf = dir ? (L_SEQ - 4 - s) : (s + 3);
            const __nv_bfloat16* src = xp + ((size_t)lf * B_N + b0) * G4;
            const uint32_t dbase = xb_u32 + (uint32_t)(((s + 3) & 3) * XB_BUFSZ * 2);
            const int brow = tid >> 6, c16 = tid & 63;
            cp16(dbase + (uint32_t)(brow * XB_STRIDE * 2 + c16 * 16),
                 src + brow * 512 + c16 * 8);
        }
        asm volatile("cp.async.commit_group;");

        // init accumulators from x (loaded early; consumed after MMA chain)
        float d[4][4];
        {
            const __nv_bfloat16* xb_base = xbuf + (s & 3) * XB_BUFSZ;
#pragma unroll
            for (int p = 0; p < 4; ++p) {
                const int br = (2 * tig + (p & 1)) & 3;
                const __nv_bfloat16* xr =
                    xb_base + br * XB_STRIDE + 16 * wid + gid + 8 * (p >> 1);
                d[0][p] = __bfloat162float(xr[0]);
                d[1][p] = __bfloat162float(xr[128]);
                d[2][p] = __bfloat162float(xr[256]);
                d[3][p] = __bfloat162float(xr[384]);
            }
        }

        uint32_t rb[8][2];
        const uint32_t base = hb_u32 + (uint32_t)((s & 1) * 2048) + ((uint32_t)(lane & 15) << 4);
#pragma unroll
        for (int ks = 0; ks < 8; ++ks) ldmatrix_x2_trans(rb[ks], base + ks * 256);

#pragma unroll
        for (int ks = 0; ks < 8; ++ks)
#pragma unroll
            for (int q = 0; q < 4; ++q) mma_bf16(d[q], afr[q][ks], rb[ks]);

        // activations straight off the accumulators
        float hv[4];
#pragma unroll
        for (int p = 0; p < 4; ++p) {
            float cn = sig_fast(d[1][p]) * cst[p] + sig_fast(d[0][p]) * tanh_fast(d[2][p]);
            cst[p] = cn;
            hv[p] = sig_fast(d[3][p]) * tanh_fast(cn);
        }

        if (live) {
            const int r0 = 16 * wid + gid;
            hbuf[((s + 1) & 1) * 512 + r0 * 4 + tig]       = bf2(hv[0], hv[1]);
            hbuf[((s + 1) & 1) * 512 + (r0 + 8) * 4 + tig] = bf2(hv[2], hv[3]);

            const size_t orow = ((size_t)l * B_N + b0 + 2 * tig) * 256;
            hout[orow + r0]           = __float2bfloat16(hv[0]);
            hout[orow + 256 + r0]     = __float2bfloat16(hv[1]);
            hout[orow + r0 + 8]       = __float2bfloat16(hv[2]);
            hout[orow + 256 + r0 + 8] = __float2bfloat16(hv[3]);
        }

        asm volatile("cp.async.wait_group 2;");   // x(s+1) ready
        __syncthreads();
    }
}

// ============================================================================
// Kernel 3: emis via HMMA. M=128 rows, N=48 tags, K=256. (unchanged)
// ============================================================================
#define EMM_A_OFF    0
#define EMM_B_OFF    (128 * 264 * 2)
#define EMM_BIAS_OFF (EMM_B_OFF + 48 * 264 * 2)
#define EMM_SMEM     (EMM_BIAS_OFF + 48 * 4)

__global__ __launch_bounds__(256) void emis_mma_kernel(const float* __restrict__ Wout,
                                                       const float* __restrict__ bout) {
    extern __shared__ char esm[];
    __nv_bfloat16* A_s = (__nv_bfloat16*)(esm + EMM_A_OFF);   // [128][264]
    __nv_bfloat16* B_s = (__nv_bfloat16*)(esm + EMM_B_OFF);   // [48][264]
    float* bias_s      = (float*)(esm + EMM_BIAS_OFF);        // [48]

    const int tid = threadIdx.x;
    const int row0 = blockIdx.x * 128;

    if (tid < 48) bias_s[tid] = bout[tid];

    {
        const int r = tid >> 1, hf = tid & 1;
        const uint4* src = (const uint4*)(g_hcat + (size_t)(row0 + r) * 256 + hf * 128);
        uint4* dst = (uint4*)(A_s + r * 264 + hf * 128);
#pragma unroll
        for (int i = 0; i < 16; ++i) dst[i] = src[i];
    }
    if (tid < 96) {
        const int r = tid >> 1, hf = tid & 1;
        const float4* src = (const float4*)(Wout + (size_t)r * 256 + hf * 128);
        __nv_bfloat16* dst = B_s + r * 264 + hf * 128;
#pragma unroll
        for (int i = 0; i < 16; ++i) {
            float4 v0 = src[2 * i], v1 = src[2 * i + 1];
            uint4 pk;
            pk.x = bf2(v0.x, v0.y);
            pk.y = bf2(v0.z, v0.w);
            pk.z = bf2(v1.x, v1.y);
            pk.w = bf2(v1.z, v1.w);
            *(uint4*)(dst + i * 8) = pk;
        }
    }
    __syncthreads();

    const uint32_t As = smem_u32(A_s), Bs = smem_u32(B_s);
    const int lane = tid & 31, wid = tid >> 5;
    const int m_base = (wid >> 1) * 32;
    const int n_base = (wid & 1) * 24;

    const int aq = lane >> 3;
    const uint32_t a_row = (uint32_t)((aq & 1) * 8 + (lane & 7));
    const uint32_t a_col = (uint32_t)((aq >> 1) * 16);
    const uint32_t b_row = (uint32_t)(lane & 7);
    const uint32_t b_col = (uint32_t)(((lane >> 3) & 1) * 16);

    float d[2][3][4];
#pragma unroll
    for (int mt = 0; mt < 2; ++mt)
#pragma unroll
        for (int nt = 0; nt < 3; ++nt)
#pragma unroll
            for (int c = 0; c < 4; ++c) d[mt][nt][c] = 0.f;

#pragma unroll
    for (int ks = 0; ks < 16; ++ks) {
        uint32_t a0[4], a1[4];
        ldsm_x4(a0, As + (m_base + 0 + a_row) * 528 + ks * 32 + a_col);
        ldsm_x4(a1, As + (m_base + 16 + a_row) * 528 + ks * 32 + a_col);
#pragma unroll
        for (int nt = 0; nt < 3; ++nt) {
            uint32_t bb[2];
            ldsm_x2(bb, Bs + (n_base + nt * 8 + b_row) * 528 + ks * 32 + b_col);
            mma_bf16(d[0][nt], a0, bb);
            mma_bf16(d[1][nt], a1, bb);
        }
    }

    const int r = lane >> 2, c = (lane & 3) * 2;
#pragma unroll
    for (int mt = 0; mt < 2; ++mt) {
        const int gr = row0 + m_base + mt * 16 + r;
#pragma unroll
        for (int nt = 0; nt < 3; ++nt) {
            const int gc = n_base + nt * 8 + c;
            const float bx = bias_s[gc], by = bias_s[gc + 1];
            float2 o0 = make_float2(d[mt][nt][0] + bx, d[mt][nt][1] + by);
            float2 o1 = make_float2(d[mt][nt][2] + bx, d[mt][nt][3] + by);
            *(float2*)(g_emis + (size_t)gr * T_TAG + gc) = o0;
            *(float2*)(g_emis + (size_t)(gr + 8) * T_TAG + gc) = o1;
        }
    }
}

// ============================================================================
// Kernel 4: CRF — fwd/bwd split, TWO sequences per warp (interleaved chains
// share E-matrix LDS operands and hide each other's latency).
// CTA = 64 threads (warp0 = fwd A+B, warp1 = bwd A+B), grid = 128.
// Final mean-reduction fused (threadfence + counter).
// ============================================================================
__global__ __launch_bounds__(64) void crf_kernel(const int* __restrict__ words,
                                                 const int* __restrict__ tags,
                                                 const float* __restrict__ trans,
                                                 const float* __restrict__ start_trans,
                                                 const float* __restrict__ end_trans,
                                                 float* __restrict__ out) {
    __shared__ __align__(16) float Efw_s[48 * 52];
    __shared__ __align__(16) float Ebw_s[48 * 52];
    __shared__ __align__(16) float tr_s[48 * 48];
    __shared__ __align__(16) float x_s[2][2][48];   // [warp][seq][state]
    __shared__ float lz_s[2][2];
    __shared__ float np_s[2][2];
    __shared__ int last_s;

    const int tid = threadIdx.x;
    const int role = tid >> 5;           // 0 = forward warp, 1 = backward warp
    const int lane = tid & 31;
    const int bA = blockIdx.x * 2;
    const int bB = bA + 1;

    for (int idx = tid; idx < 48 * 48; idx += 64) {
        float v = trans[idx];
        tr_s[idx] = v;
        float e = __expf(v);
        const int i = idx / 48, j = idx - i * 48;
        Efw_s[j * 52 + i] = e;
        Ebw_s[i * 52 + j] = e;
    }
    __syncthreads();

    // lengths of both sequences (packed int warp reduce)
    int cA = 0, cB = 0;
    for (int l = lane; l < L_SEQ; l += 32) {
        cA += (words[bA * L_SEQ + l] != 0) ? 1 : 0;
        cB += (words[bB * L_SEQ + l] != 0) ? 1 : 0;
    }
    int packed = warp_sum_i(cA | (cB << 16));
    const int lenA = packed & 0xFFFF;
    const int lenB = packed >> 16;
    const int midA = lenA >> 1;
    const int midB = lenB >> 1;

    const int j1 = lane;
    const int j2 = 32 + lane;
    const bool has2 = lane < 16;
    const ulonglong2* m1 = (const ulonglong2*)((role ? Ebw_s : Efw_s) + j1 * 52);
    const ulonglong2* m2 = (const ulonglong2*)((role ? Ebw_s : Efw_s) + j2 * 52);

    // ---- numerator partials (both seqs) ----
    {
        float npA = 0.f, npB = 0.f;
        {
            const int lo = role ? (midA + 1) : 1;
            const int hi = role ? lenA : (midA + 1);
            for (int l = lo + lane; l < hi; l += 32) {
                int tp = tags[bA * L_SEQ + l - 1];
                int tc = tags[bA * L_SEQ + l];
                npA += tr_s[tp * 48 + tc] + g_emis[((size_t)l * B_N + bA) * T_TAG + tc];
            }
        }
        {
            const int lo = role ? (midB + 1) : 1;
            const int hi = role ? lenB : (midB + 1);
            for (int l = lo + lane; l < hi; l += 32) {
                int tp = tags[bB * L_SEQ + l - 1];
                int tc = tags[bB * L_SEQ + l];
                npB += tr_s[tp * 48 + tc] + g_emis[((size_t)l * B_N + bB) * T_TAG + tc];
            }
        }
        npA = warp_sum(npA);
        npB = warp_sum(npB);
        if (lane == 0) {
            if (role == 0) {
                int tA = tags[bA * L_SEQ], tB = tags[bB * L_SEQ];
                npA += start_trans[tA] + g_emis[(size_t)bA * T_TAG + tA];
                npB += start_trans[tB] + g_emis[(size_t)bB * T_TAG + tB];
            } else {
                npA += end_trans[tags[bA * L_SEQ + (lenA - 1)]];
                npB += end_trans[tags[bB * L_SEQ + (lenB - 1)]];
            }
            np_s[role][0] = npA;
            np_s[role][1] = npB;
        }
    }

    // ---- init vectors ----
    float pA1, pA2, pB1, pB2, lzA = 0.f, lzB = 0.f;
    if (role == 0) {
        pA1 = __expf(start_trans[j1] + g_emis[(size_t)bA * T_TAG + j1]);
        pA2 = has2 ? __expf(start_trans[j2] + g_emis[(size_t)bA * T_TAG + j2]) : 0.f;
        pB1 = __expf(start_trans[j1] + g_emis[(size_t)bB * T_TAG + j1]);
        pB2 = has2 ? __expf(start_trans[j2] + g_emis[(size_t)bB * T_TAG + j2]) : 0.f;
    } else {
        pA1 = __expf(end_trans[j1]);
        pA2 = has2 ? __expf(end_trans[j2]) : 0.f;
        pB1 = pA1;
        pB2 = pA2;
    }

    const int nsA = role ? (lenA - 1 - midA) : midA;
    const int nsB = role ? (lenB - 1 - midB) : midB;
    const int maxns = (nsA > nsB) ? nsA : nsB;

    // emission pipelines, 4 deep, per seq (fwd: l=1+t; bwd: l=len-1-t)
    float eA1[4], eA2[4], eB1[4], eB2[4];
#pragma unroll
    for (int k = 0; k < 4; ++k) {
        eA1[k] = eA2[k] = eB1[k] = eB2[k] = 0.f;
        if (k < nsA) {
            const int ei = role ? (lenA - 1 - k) : (1 + k);
            const size_t eb = ((size_t)ei * B_N + bA) * T_TAG;
            eA1[k] = g_emis[eb + j1];
            eA2[k] = has2 ? g_emis[eb + j2] : 0.f;
        }
        if (k < nsB) {
            const int ei = role ? (lenB - 1 - k) : (1 + k);
            const size_t eb = ((size_t)ei * B_N + bB) * T_TAG;
            eB1[k] = g_emis[eb + j1];
            eB2[k] = has2 ? g_emis[eb + j2] : 0.f;
        }
    }

    for (int t = 0; t < maxns; ++t) {
        const bool actA = t < nsA;
        const bool actB = t < nsB;

        // prefetch t+4 emissions
        float fA1 = 0.f, fA2 = 0.f, fB1 = 0.f, fB2 = 0.f;
        if (t + 4 < nsA) {
            const int ei = role ? (lenA - 5 - t) : (5 + t);
            const size_t eb = ((size_t)ei * B_N + bA) * T_TAG;
            fA1 = g_emis[eb + j1];
            fA2 = has2 ? g_emis[eb + j2] : 0.f;
        }
        if (t + 4 < nsB) {
            const int ei = role ? (lenB - 5 - t) : (5 + t);
            const size_t eb = ((size_t)ei * B_N + bB) * T_TAG;
            fB1 = g_emis[eb + j1];
            fB2 = has2 ? g_emis[eb + j2] : 0.f;
        }

        // publish x (fwd: raw p; bwd: p * e^{em})
        if (actA) {
            float x1 = role ? pA1 * __expf(eA1[0]) : pA1;
            x_s[role][0][j1] = x1;
            if (has2) x_s[role][0][j2] = role ? pA2 * __expf(eA2[0]) : pA2;
        }
        if (actB) {
            float x1 = role ? pB1 * __expf(eB1[0]) : pB1;
            x_s[role][1][j1] = x1;
            if (has2) x_s[role][1][j2] = role ? pB2 * __expf(eB2[0]) : pB2;
        }
        __syncwarp();

        // shared-operand dual matvec (A and B chains interleaved)
        ull Aa0 = 0ull, Aa1 = 0ull, Ba0 = 0ull, Ba1 = 0ull;   // seq A: j1, j2
        ull Ab0 = 0ull, Ab1 = 0ull, Bb0 = 0ull, Bb1 = 0ull;   // seq B: j1, j2
        const ulonglong2* pxA = (const ulonglong2*)x_s[role][0];
        const ulonglong2* pxB = (const ulonglong2*)x_s[role][1];
#pragma unroll
        for (int i4 = 0; i4 < 12; ++i4) {
            ulonglong2 pvA = pxA[i4];
            ulonglong2 pvB = pxB[i4];
            ulonglong2 mv1 = m1[i4];
            ffma2(Aa0, pvA.x, mv1.x);
            ffma2(Aa1, pvA.y, mv1.y);
            ffma2(Ab0, pvB.x, mv1.x);
            ffma2(Ab1, pvB.y, mv1.y);
            if (has2) {
                ulonglong2 mv2 = m2[i4];
                ffma2(Ba0, pvA.x, mv2.x);
                ffma2(Ba1, pvA.y, mv2.y);
                ffma2(Bb0, pvB.x, mv2.x);
                ffma2(Bb1, pvB.y, mv2.y);
            }
        }

        if (actA) {
            float2 u0 = unpack2(Aa0), u1 = unpack2(Aa1);
            float s1 = (u0.x + u0.y) + (u1.x + u1.y);
            float2 v0 = unpack2(Ba0), v1 = unpack2(Ba1);
            float s2 = (v0.x + v0.y) + (v1.x + v1.y);
            pA1 = role ? s1 : s1 * __expf(eA1[0]);
            pA2 = has2 ? (role ? s2 : s2 * __expf(eA2[0])) : 0.f;
            eA1[0] = eA1[1]; eA1[1] = eA1[2]; eA1[2] = eA1[3]; eA1[3] = fA1;
            eA2[0] = eA2[1]; eA2[1] = eA2[2]; eA2[2] = eA2[3]; eA2[3] = fA2;
            if ((t & 3) == 3) {
                float S = warp_sum(pA1 + pA2);
                float inv = 1.f / S;
                pA1 *= inv;
                pA2 *= inv;
                lzA += __logf(S);
            }
        }
        if (actB) {
            float2 u0 = unpack2(Ab0), u1 = unpack2(Ab1);
            float s1 = (u0.x + u0.y) + (u1.x + u1.y);
            float2 v0 = unpack2(Bb0), v1 = unpack2(Bb1);
            float s2 = (v0.x + v0.y) + (v1.x + v1.y);
            pB1 = role ? s1 : s1 * __expf(eB1[0]);
            pB2 = has2 ? (role ? s2 : s2 * __expf(eB2[0])) : 0.f;
            eB1[0] = eB1[1]; eB1[1] = eB1[2]; eB1[2] = eB1[3]; eB1[3] = fB1;
            eB2[0] = eB2[1]; eB2[1] = eB2[2]; eB2[2] = eB2[3]; eB2[3] = fB2;
            if ((t & 3) == 3) {
                float S = warp_sum(pB1 + pB2);
                float inv = 1.f / S;
                pB1 *= inv;
                pB2 *= inv;
                lzB += __logf(S);
            }
        }
        __syncwarp();
    }

    // publish finals
    x_s[role][0][j1] = pA1;
    x_s[role][1][j1] = pB1;
    if (has2) {
        x_s[role][0][j2] = pA2;
        x_s[role][1][j2] = pB2;
    }
    if (lane == 0) {
        lz_s[role][0] = lzA;
        lz_s[role][1] = lzB;
    }
    __syncthreads();

    if (role == 0) {
        float dA = x_s[0][0][j1] * x_s[1][0][j1];
        float dB = x_s[0][1][j1] * x_s[1][1][j1];
        if (has2) {
            dA += x_s[0][0][j2] * x_s[1][0][j2];
            dB += x_s[0][1][j2] * x_s[1][1][j2];
        }
        dA = warp_sum(dA);
        dB = warp_sum(dB);
        if (lane == 0) {
            g_llh[bA] = (np_s[0][0] + np_s[1][0]) -
                        (lz_s[0][0] + lz_s[1][0] + __logf(dA));
            g_llh[bB] = (np_s[0][1] + np_s[1][1]) -
                        (lz_s[0][1] + lz_s[1][1] + __logf(dB));
        }
    }

    // ---- fused final reduction: last CTA computes -mean(llh) ----
    __syncthreads();
    if (tid == 0) {
        __threadfence();
        int prev = atomicAdd(&g_crf_ctr, 1);
        last_s = (prev == (int)gridDim.x - 1) ? 1 : 0;
    }
    __syncthreads();
    if (last_s) {
        __shared__ float red[64];
        float v = g_llh[tid] + g_llh[tid + 64] + g_llh[tid + 128] + g_llh[tid + 192];
        red[tid] = v;
        __syncthreads();
        for (int s = 32; s > 0; s >>= 1) {
            if (tid < s) red[tid] += red[tid + s];
            __syncthreads();
        }
        if (tid == 0) {
            out[0] = -red[0] / (float)B_N;
            g_crf_ctr = 0;   // reset for next (deterministic) run
        }
    }
}

// ============================================================================
// launch
// ============================================================================
extern "C" void kernel_launch(void* const* d_in, const int* in_sizes, int n_in,
                              void* d_out, int out_size) {
    const int*   words  = (const int*)d_in[0];
    const int*   tags   = (const int*)d_in[1];
    // d_in[2] = mask (unused; derived from words != 0)
    const float* emb    = (const float*)d_in[3];
    const float* Wih_f  = (const float*)d_in[4];
    const float* Whh_f  = (const float*)d_in[5];
    const float* bih_f  = (const float*)d_in[6];
    const float* bhh_f  = (const float*)d_in[7];
    const float* Wih_b  = (const float*)d_in[8];
    const float* Whh_b  = (const float*)d_in[9];
    const float* bih_b  = (const float*)d_in[10];
    const float* bhh_b  = (const float*)d_in[11];
    const float* Wout   = (const float*)d_in[12];
    const float* bout   = (const float*)d_in[13];
    const float* trans  = (const float*)d_in[14];
    const float* st     = (const float*)d_in[15];
    const float* et     = (const float*)d_in[16];
    float* out = (float*)d_out;

    cudaFuncSetAttribute(xproj_mma_kernel, cudaFuncAttributeMaxDynamicSharedMemorySize,
                         XPM_SMEM);
    cudaFuncSetAttribute(lstm_mma_kernel, cudaFuncAttributeMaxDynamicSharedMemorySize,
                         LSTM_SMEM);
    cudaFuncSetAttribute(emis_mma_kernel, cudaFuncAttributeMaxDynamicSharedMemorySize,
                         EMM_SMEM);

    // 1) input projections via HMMA (bf16 output)
    xproj_mma_kernel<<<dim3(4, (L_SEQ * B_N) / 128, 2), 256, XPM_SMEM>>>(
        words, emb, Wih_f, bih_f, bhh_f, Wih_b, bih_b, bhh_b);

    // 2) HMMA BiLSTM: NB=4 -> 64 CTAs x 2 dirs = 128 CTAs (1/SM)
    lstm_mma_kernel<<<dim3(B_N / NB, 2), 256, LSTM_SMEM>>>(Whh_f, Whh_b);

    // 3) emissions via HMMA
    emis_mma_kernel<<<(L_SEQ * B_N) / 128, 256, EMM_SMEM>>>(Wout, bout);

    // 4) CRF: 2 seqs/warp fwd-bwd split (fused final reduction)
    crf_kernel<<<B_N / 2, 64>>>(words, tags, trans, st, et, out);
}

// round 14
// speedup vs baseline: 1.2914x; 1.2914x over previous
#include <cuda_runtime.h>
#include <cuda_fp16.h>
#include <cuda_bf16.h>
#include <cstdint>

// ---------------- problem constants ----------------
#define L_SEQ 512
#define B_N   256
#define E_DIM 128
#define H_DIM 128
#define G4    512     // 4*H
#define T_TAG 48
#define NB    4       // batch lanes per LSTM CTA (half of mma N=8 tile)

typedef unsigned long long ull;

// ---------------- scratch (device globals; no allocation allowed) ----------------
__device__ __nv_bfloat16 g_xproj_f[(size_t)L_SEQ * B_N * G4];   // 128 MiB
__device__ __nv_bfloat16 g_xproj_b[(size_t)L_SEQ * B_N * G4];   // 128 MiB
__device__ __nv_bfloat16 g_hcat[(size_t)L_SEQ * B_N * 256];     // 64 MiB [l][b][2H]
__device__ float g_emis[(size_t)L_SEQ * B_N * T_TAG];           // 24 MiB
__device__ float g_llh[B_N];
__device__ int   g_crf_ctr;                                     // zero-init; reset each run

// ---------------- generic helpers ----------------
__device__ __forceinline__ float tanh_fast(float x) {
    float y;
    asm("tanh.approx.f32 %0, %1;" : "=f"(y) : "f"(x));
    return y;
}
__device__ __forceinline__ float sig_fast(float x) {
    return fmaf(0.5f, tanh_fast(0.5f * x), 0.5f);
}
__device__ __forceinline__ uint32_t smem_u32(const void* p) {
    uint32_t a;
    asm("{ .reg .u64 t; cvta.to.shared.u64 t, %1; cvt.u32.u64 %0, t; }" : "=r"(a) : "l"(p));
    return a;
}
__device__ __forceinline__ uint32_t bf2(float x, float y) {
    __nv_bfloat162 t = __floats2bfloat162_rn(x, y);
    return *(uint32_t*)&t;
}
__device__ __forceinline__ void ffma2(ull& d, ull a, ull b) {
    asm("fma.rn.f32x2 %0, %1, %2, %0;" : "+l"(d) : "l"(a), "l"(b));
}
__device__ __forceinline__ float2 unpack2(ull v) {
    float2 r;
    asm("mov.b64 {%0, %1}, %2;" : "=f"(r.x), "=f"(r.y) : "l"(v));
    return r;
}
__device__ __forceinline__ void mma_bf16(float* d, const uint32_t* a, const uint32_t* b) {
    asm volatile(
        "mma.sync.aligned.m16n8k16.row.col.f32.bf16.bf16.f32 "
        "{%0,%1,%2,%3}, {%4,%5,%6,%7}, {%8,%9}, {%0,%1,%2,%3};"
        : "+f"(d[0]), "+f"(d[1]), "+f"(d[2]), "+f"(d[3])
        : "r"(a[0]), "r"(a[1]), "r"(a[2]), "r"(a[3]), "r"(b[0]), "r"(b[1]));
}
__device__ __forceinline__ void ldmatrix_x2_trans(uint32_t* r, uint32_t addr) {
    asm volatile("ldmatrix.sync.aligned.m8n8.x2.trans.shared.b16 {%0,%1}, [%2];"
                 : "=r"(r[0]), "=r"(r[1]) : "r"(addr));
}
__device__ __forceinline__ void ldsm_x4(uint32_t* r, uint32_t a) {
    asm volatile("ldmatrix.sync.aligned.m8n8.x4.shared.b16 {%0,%1,%2,%3}, [%4];"
                 : "=r"(r[0]), "=r"(r[1]), "=r"(r[2]), "=r"(r[3]) : "r"(a));
}
__device__ __forceinline__ void ldsm_x2(uint32_t* r, uint32_t a) {
    asm volatile("ldmatrix.sync.aligned.m8n8.x2.shared.b16 {%0,%1}, [%2];"
                 : "=r"(r[0]), "=r"(r[1]) : "r"(a));
}
__device__ __forceinline__ void cp16(uint32_t dst, const void* src) {
    asm volatile("cp.async.ca.shared.global [%0], [%1], 16;" :: "r"(dst), "l"(src));
}
__device__ __forceinline__ float warp_sum(float v) {
#pragma unroll
    for (int o = 16; o; o >>= 1) v += __shfl_xor_sync(0xFFFFFFFFu, v, o);
    return v;
}

// ============================================================================
// Kernel 1: xproj = emb[words] @ Wih^T + (bih+bhh) via HMMA bf16, bf16 output.
// CTA tile: 128 rows x 128 gates, K=128. (R12 form, unchanged)
// ============================================================================
#define XPM_A_OFF    0
#define XPM_B_OFF    (128 * 136 * 2)
#define XPM_BIAS_OFF (2 * 128 * 136 * 2)
#define XPM_SMEM     (XPM_BIAS_OFF + 128 * 4)

__global__ __launch_bounds__(256) void xproj_mma_kernel(
    const int* __restrict__ words, const float* __restrict__ emb,
    const float* __restrict__ Wih_f, const float* __restrict__ bih_f,
    const float* __restrict__ bhh_f, const float* __restrict__ Wih_b,
    const float* __restrict__ bih_b, const float* __restrict__ bhh_b) {
    extern __shared__ char xsm[];
    __nv_bfloat16* A_s = (__nv_bfloat16*)(xsm + XPM_A_OFF);   // [128][136]
    __nv_bfloat16* B_s = (__nv_bfloat16*)(xsm + XPM_B_OFF);   // [128][136]
    float* bias_s      = (float*)(xsm + XPM_BIAS_OFF);        // [128]

    const int dir = blockIdx.z;
    const float* Wih = dir ? Wih_b : Wih_f;
    const float* b1  = dir ? bih_b : bih_f;
    const float* b2  = dir ? bhh_b : bhh_f;
    __nv_bfloat16* out = dir ? g_xproj_b : g_xproj_f;

    const int row0 = blockIdx.y * 128;
    const int n0   = blockIdx.x * 128;
    const int tid  = threadIdx.x;

    if (tid < 128) bias_s[tid] = b1[n0 + tid] + b2[n0 + tid];

    {
        const int r = tid >> 1, hf = tid & 1;
        const int grow = row0 + r;
        const int l = grow >> 8, b = grow & 255;
        const int w = words[b * L_SEQ + l];
        const float4* src = (const float4*)(emb + (size_t)w * E_DIM + hf * 64);
        __nv_bfloat16* dst = A_s + r * 136 + hf * 64;
#pragma unroll
        for (int i = 0; i < 8; ++i) {
            float4 v0 = src[2 * i], v1 = src[2 * i + 1];
            uint4 pk;
            pk.x = bf2(v0.x, v0.y);
            pk.y = bf2(v0.z, v0.w);
            pk.z = bf2(v1.x, v1.y);
            pk.w = bf2(v1.z, v1.w);
            *(uint4*)(dst + i * 8) = pk;
        }
    }
    {
        const int r = tid >> 1, hf = tid & 1;
        const float4* src = (const float4*)(Wih + (size_t)(n0 + r) * E_DIM + hf * 64);
        __nv_bfloat16* dst = B_s + r * 136 + hf * 64;
#pragma unroll
        for (int i = 0; i < 8; ++i) {
            float4 v0 = src[2 * i], v1 = src[2 * i + 1];
            uint4 pk;
            pk.x = bf2(v0.x, v0.y);
            pk.y = bf2(v0.z, v0.w);
            pk.z = bf2(v1.x, v1.y);
            pk.w = bf2(v1.z, v1.w);
            *(uint4*)(dst + i * 8) = pk;
        }
    }
    __syncthreads();

    const uint32_t As = smem_u32(A_s), Bs = smem_u32(B_s);
    const int lane = tid & 31, wid = tid >> 5;
    const int m_base = (wid >> 1) * 32;
    const int n_base = (wid & 1) * 64;

    float d[2][8][4];
#pragma unroll
    for (int mt = 0; mt < 2; ++mt)
#pragma unroll
        for (int nt = 0; nt < 8; ++nt)
#pragma unroll
            for (int c = 0; c < 4; ++c) d[mt][nt][c] = 0.f;

    const int aq = lane >> 3;
    const uint32_t a_row = (uint32_t)((aq & 1) * 8 + (lane & 7));
    const uint32_t a_col = (uint32_t)((aq >> 1) * 16);
    const uint32_t b_row = (uint32_t)(lane & 7);
    const uint32_t b_col = (uint32_t)(((lane >> 3) & 1) * 16);

#pragma unroll
    for (int ks = 0; ks < 8; ++ks) {
        uint32_t a0[4], a1[4];
        ldsm_x4(a0, As + (m_base + 0 + a_row) * 272 + ks * 32 + a_col);
        ldsm_x4(a1, As + (m_base + 16 + a_row) * 272 + ks * 32 + a_col);
#pragma unroll
        for (int nt = 0; nt < 8; ++nt) {
            uint32_t bb[2];
            ldsm_x2(bb, Bs + (n_base + nt * 8 + b_row) * 272 + ks * 32 + b_col);
            mma_bf16(d[0][nt], a0, bb);
            mma_bf16(d[1][nt], a1, bb);
        }
    }

    const int r = lane >> 2, c = (lane & 3) * 2;
#pragma unroll
    for (int mt = 0; mt < 2; ++mt) {
        const int gr = row0 + m_base + mt * 16 + r;
#pragma unroll
        for (int nt = 0; nt < 8; ++nt) {
            const int gc = n_base + nt * 8 + c;
            const float bx = bias_s[gc], by = bias_s[gc + 1];
            *(uint32_t*)(out + (size_t)gr * G4 + n0 + gc) =
                bf2(d[mt][nt][0] + bx, d[mt][nt][1] + by);
            *(uint32_t*)(out + (size_t)(gr + 8) * G4 + n0 + gc) =
                bf2(d[mt][nt][2] + bx, d[mt][nt][3] + by);
        }
    }
}

// ============================================================================
// Kernel 2: HMMA LSTM (R12 form: MMA on zero accumulators, x added post-MMA).
// 256 threads, NB=4 batch/CTA (128 CTAs -> 1/SM), 4-buffer cp.async staging.
// ============================================================================
#define LSTM_HBUF   0
#define LSTM_XBUF   4096
#define XB_STRIDE   520                       // bf16 units per batch row
#define XB_BUFSZ    (4 * XB_STRIDE)           // bf16 units per buffer
#define LSTM_SMEM   (4096 + 4 * XB_BUFSZ * 2)

__global__ __launch_bounds__(256) void lstm_mma_kernel(const float* __restrict__ Whh_f,
                                                       const float* __restrict__ Whh_b) {
    extern __shared__ char smraw[];
    uint32_t* hbuf      = (uint32_t*)(smraw + LSTM_HBUF);       // [2][128][4 bf16x2]
    __nv_bfloat16* xbuf = (__nv_bfloat16*)(smraw + LSTM_XBUF);  // [4][4][520]

    const int tid  = threadIdx.x;
    const int lane = tid & 31;
    const int wid  = tid >> 5;
    const int gid  = lane >> 2;
    const int tig  = lane & 3;
    const int dir  = blockIdx.y;
    const int b0   = blockIdx.x * NB;
    const float* Whh = dir ? Whh_b : Whh_f;
    const __nv_bfloat16* xp = dir ? g_xproj_b : g_xproj_f;
    __nv_bfloat16* hout     = g_hcat + dir * 128;

    const uint32_t hb_u32 = smem_u32(hbuf);
    const uint32_t xb_u32 = smem_u32(xbuf);
    const bool live = (tig < 2);   // batches 2*tig, 2*tig+1 in [0,4)

    uint32_t afr[4][8][4];
#pragma unroll
    for (int q = 0; q < 4; ++q) {
        const int r0 = 16 * wid + 128 * q + gid;
#pragma unroll
        for (int ks = 0; ks < 8; ++ks) {
            const int cc = ks * 16 + 2 * tig;
            float2 v00 = *(const float2*)(Whh + (size_t)r0 * 128 + cc);
            float2 v10 = *(const float2*)(Whh + (size_t)(r0 + 8) * 128 + cc);
            float2 v01 = *(const float2*)(Whh + (size_t)r0 * 128 + cc + 8);
            float2 v11 = *(const float2*)(Whh + (size_t)(r0 + 8) * 128 + cc + 8);
            afr[q][ks][0] = bf2(v00.x, v00.y);
            afr[q][ks][1] = bf2(v10.x, v10.y);
            afr[q][ks][2] = bf2(v01.x, v01.y);
            afr[q][ks][3] = bf2(v11.x, v11.y);
        }
    }

    for (int i = tid; i < 2 * 128 * 4; i += 256) hbuf[i] = 0;

    // prologue: prefetch x(0..2) — 256 x 16B per buffer (1 cp16/thread)
#pragma unroll
    for (int ps = 0; ps < 3; ++ps) {
        const int l = dir ? (L_SEQ - 1 - ps) : ps;
        const __nv_bfloat16* src = xp + ((size_t)l * B_N + b0) * G4;
        const int brow = tid >> 6, c16 = tid & 63;
        cp16(xb_u32 + (uint32_t)(ps * XB_BUFSZ * 2 + brow * XB_STRIDE * 2 + c16 * 16),
             src + brow * 512 + c16 * 8);
        asm volatile("cp.async.commit_group;");
    }
    asm volatile("cp.async.wait_group 2;");   // x(0) ready
    __syncthreads();

    float cst[4] = {0.f, 0.f, 0.f, 0.f};

    for (int s = 0; s < L_SEQ; ++s) {
        const int l = dir ? (L_SEQ - 1 - s) : s;

        // issue prefetch x(s+3) (group always committed to keep the count)
        if (s + 3 < L_SEQ) {
            const int lf = dir ? (L_SEQ - 4 - s) : (s + 3);
            const __nv_bfloat16* src = xp + ((size_t)lf * B_N + b0) * G4;
            const uint32_t dbase = xb_u32 + (uint32_t)(((s + 3) & 3) * XB_BUFSZ * 2);
            const int brow = tid >> 6, c16 = tid & 63;
            cp16(dbase + (uint32_t)(brow * XB_STRIDE * 2 + c16 * 16),
                 src + brow * 512 + c16 * 8);
        }
        asm volatile("cp.async.commit_group;");

        uint32_t rb[8][2];
        const uint32_t base = hb_u32 + (uint32_t)((s & 1) * 2048) + ((uint32_t)(lane & 15) << 4);
#pragma unroll
        for (int ks = 0; ks < 8; ++ks) ldmatrix_x2_trans(rb[ks], base + ks * 256);

        float d[4][4];
#pragma unroll
        for (int q = 0; q < 4; ++q)
#pragma unroll
            for (int c = 0; c < 4; ++c) d[q][c] = 0.f;
#pragma unroll
        for (int ks = 0; ks < 8; ++ks)
#pragma unroll
            for (int q = 0; q < 4; ++q) mma_bf16(d[q], afr[q][ks], rb[ks]);

        // activations (live lanes carry real batches; dead lanes bounded garbage)
        const __nv_bfloat16* xb_base = xbuf + (s & 3) * XB_BUFSZ;
        float hv[4];
#pragma unroll
        for (int p = 0; p < 4; ++p) {
            const int br = (2 * tig + (p & 1)) & 3;
            const __nv_bfloat16* xr = xb_base + br * XB_STRIDE + 16 * wid + gid + 8 * (p >> 1);
            float gi = d[0][p] + __bfloat162float(xr[0]);
            float gf = d[1][p] + __bfloat162float(xr[128]);
            float gg = d[2][p] + __bfloat162float(xr[256]);
            float go = d[3][p] + __bfloat162float(xr[384]);
            float cn = sig_fast(gf) * cst[p] + sig_fast(gi) * tanh_fast(gg);
            cst[p] = cn;
            hv[p] = sig_fast(go) * tanh_fast(cn);
        }

        if (live) {
            const int r0 = 16 * wid + gid;
            hbuf[((s + 1) & 1) * 512 + r0 * 4 + tig]       = bf2(hv[0], hv[1]);
            hbuf[((s + 1) & 1) * 512 + (r0 + 8) * 4 + tig] = bf2(hv[2], hv[3]);

            const size_t orow = ((size_t)l * B_N + b0 + 2 * tig) * 256;
            hout[orow + r0]           = __float2bfloat16(hv[0]);
            hout[orow + 256 + r0]     = __float2bfloat16(hv[1]);
            hout[orow + r0 + 8]       = __float2bfloat16(hv[2]);
            hout[orow + 256 + r0 + 8] = __float2bfloat16(hv[3]);
        }

        asm volatile("cp.async.wait_group 2;");   // x(s+1) ready
        __syncthreads();
    }
}

// ============================================================================
// Kernel 3: emis via HMMA. M=128 rows, N=48 tags, K=256. (unchanged)
// ============================================================================
#define EMM_A_OFF    0
#define EMM_B_OFF    (128 * 264 * 2)
#define EMM_BIAS_OFF (EMM_B_OFF + 48 * 264 * 2)
#define EMM_SMEM     (EMM_BIAS_OFF + 48 * 4)

__global__ __launch_bounds__(256) void emis_mma_kernel(const float* __restrict__ Wout,
                                                       const float* __restrict__ bout) {
    extern __shared__ char esm[];
    __nv_bfloat16* A_s = (__nv_bfloat16*)(esm + EMM_A_OFF);   // [128][264]
    __nv_bfloat16* B_s = (__nv_bfloat16*)(esm + EMM_B_OFF);   // [48][264]
    float* bias_s      = (float*)(esm + EMM_BIAS_OFF);        // [48]

    const int tid = threadIdx.x;
    const int row0 = blockIdx.x * 128;

    if (tid < 48) bias_s[tid] = bout[tid];

    {
        const int r = tid >> 1, hf = tid & 1;
        const uint4* src = (const uint4*)(g_hcat + (size_t)(row0 + r) * 256 + hf * 128);
        uint4* dst = (uint4*)(A_s + r * 264 + hf * 128);
#pragma unroll
        for (int i = 0; i < 16; ++i) dst[i] = src[i];
    }
    if (tid < 96) {
        const int r = tid >> 1, hf = tid & 1;
        const float4* src = (const float4*)(Wout + (size_t)r * 256 + hf * 128);
        __nv_bfloat16* dst = B_s + r * 264 + hf * 128;
#pragma unroll
        for (int i = 0; i < 16; ++i) {
            float4 v0 = src[2 * i], v1 = src[2 * i + 1];
            uint4 pk;
            pk.x = bf2(v0.x, v0.y);
            pk.y = bf2(v0.z, v0.w);
            pk.z = bf2(v1.x, v1.y);
            pk.w = bf2(v1.z, v1.w);
            *(uint4*)(dst + i * 8) = pk;
        }
    }
    __syncthreads();

    const uint32_t As = smem_u32(A_s), Bs = smem_u32(B_s);
    const int lane = tid & 31, wid = tid >> 5;
    const int m_base = (wid >> 1) * 32;
    const int n_base = (wid & 1) * 24;

    const int aq = lane >> 3;
    const uint32_t a_row = (uint32_t)((aq & 1) * 8 + (lane & 7));
    const uint32_t a_col = (uint32_t)((aq >> 1) * 16);
    const uint32_t b_row = (uint32_t)(lane & 7);
    const uint32_t b_col = (uint32_t)(((lane >> 3) & 1) * 16);

    float d[2][3][4];
#pragma unroll
    for (int mt = 0; mt < 2; ++mt)
#pragma unroll
        for (int nt = 0; nt < 3; ++nt)
#pragma unroll
            for (int c = 0; c < 4; ++c) d[mt][nt][c] = 0.f;

#pragma unroll
    for (int ks = 0; ks < 16; ++ks) {
        uint32_t a0[4], a1[4];
        ldsm_x4(a0, As + (m_base + 0 + a_row) * 528 + ks * 32 + a_col);
        ldsm_x4(a1, As + (m_base + 16 + a_row) * 528 + ks * 32 + a_col);
#pragma unroll
        for (int nt = 0; nt < 3; ++nt) {
            uint32_t bb[2];
            ldsm_x2(bb, Bs + (n_base + nt * 8 + b_row) * 528 + ks * 32 + b_col);
            mma_bf16(d[0][nt], a0, bb);
            mma_bf16(d[1][nt], a1, bb);
        }
    }

    const int r = lane >> 2, c = (lane & 3) * 2;
#pragma unroll
    for (int mt = 0; mt < 2; ++mt) {
        const int gr = row0 + m_base + mt * 16 + r;
#pragma unroll
        for (int nt = 0; nt < 3; ++nt) {
            const int gc = n_base + nt * 8 + c;
            const float bx = bias_s[gc], by = bias_s[gc + 1];
            float2 o0 = make_float2(d[mt][nt][0] + bx, d[mt][nt][1] + by);
            float2 o1 = make_float2(d[mt][nt][2] + bx, d[mt][nt][3] + by);
            *(float2*)(g_emis + (size_t)gr * T_TAG + gc) = o0;
            *(float2*)(g_emis + (size_t)(gr + 8) * T_TAG + gc) = o1;
        }
    }
}

// ============================================================================
// Kernel 4: CRF — fwd/bwd split, 2 warps/sequence, 2 sequences/CTA (R12 form)
// + e-row for j1 hoisted to registers (24 ull), m2 stays in smem
// + renorm every 8 steps. Fused final reduction.
// ============================================================================
__global__ __launch_bounds__(128, 1) void crf_kernel(const int* __restrict__ words,
                                                     const int* __restrict__ tags,
                                                     const float* __restrict__ trans,
                                                     const float* __restrict__ start_trans,
                                                     const float* __restrict__ end_trans,
                                                     float* __restrict__ out) {
    __shared__ __align__(16) float Efw_s[48 * 52];
    __shared__ __align__(16) float Ebw_s[48 * 52];
    __shared__ __align__(16) float tr_s[48 * 48];
    __shared__ __align__(16) float x_s[4][48];
    __shared__ float lz_s[4];
    __shared__ float np_s[4];
    __shared__ int last_s;

    const int tid = threadIdx.x;
    const int wid = tid >> 5, lane = tid & 31;
    const int role = wid & 1;            // 0 = forward, 1 = backward
    const int b = blockIdx.x * 2 + (wid >> 1);

    for (int idx = tid; idx < 48 * 48; idx += 128) {
        float v = trans[idx];
        tr_s[idx] = v;
        float e = __expf(v);
        const int i = idx / 48, j = idx - i * 48;
        Efw_s[j * 52 + i] = e;
        Ebw_s[i * 52 + j] = e;
    }
    __syncthreads();

    // sequence length (prefix mask == words != 0)
    int cnt = 0;
    for (int l = lane; l < L_SEQ; l += 32) cnt += (words[b * L_SEQ + l] != 0) ? 1 : 0;
#pragma unroll
    for (int o = 16; o; o >>= 1) cnt += __shfl_xor_sync(0xFFFFFFFFu, cnt, o);
    const int len = cnt;
    const int c = len >> 1;

    const int j1 = lane;
    const int j2 = 32 + lane;
    const bool has2 = lane < 16;

    // hoist this lane's own E row (j1) into registers: 24 ull = 48 floats
    ull e1r[24];
    {
        const ull* src = (const ull*)((role ? Ebw_s : Efw_s) + j1 * 52);
#pragma unroll
        for (int i = 0; i < 24; ++i) e1r[i] = src[i];
    }
    const ulonglong2* m2 = (const ulonglong2*)((role ? Ebw_s : Efw_s) + j2 * 52);

    // ---- numerator partial ----
    {
        const int lo = role ? (c + 1) : 1;
        const int hi = role ? len : (c + 1);
        float np = 0.f;
        for (int l = lo + lane; l < hi; l += 32) {
            int tp = tags[b * L_SEQ + l - 1];
            int tc = tags[b * L_SEQ + l];
            np += tr_s[tp * 48 + tc] + g_emis[((size_t)l * B_N + b) * T_TAG + tc];
        }
        np = warp_sum(np);
        if (lane == 0) {
            if (role == 0) {
                int t0 = tags[b * L_SEQ];
                np += start_trans[t0] + g_emis[(size_t)b * T_TAG + t0];
            } else {
                np += end_trans[tags[b * L_SEQ + (len - 1)]];
            }
            np_s[wid] = np;
        }
    }

    // ---- init vector ----
    float p1, p2, logZ = 0.f;
    if (role == 0) {
        p1 = __expf(start_trans[j1] + g_emis[(size_t)b * T_TAG + j1]);
        p2 = has2 ? __expf(start_trans[j2] + g_emis[(size_t)b * T_TAG + j2]) : 0.f;
    } else {
        p1 = __expf(end_trans[j1]);
        p2 = has2 ? __expf(end_trans[j2]) : 0.f;
    }

    const int nsteps = role ? (len - 1 - c) : c;

    // emission position for step t: fwd -> 1+t, bwd -> len-1-t.  4-deep pipeline.
    float e1p0 = 0.f, e1p1 = 0.f, e1p2 = 0.f, e1p3 = 0.f;
    float e2p0 = 0.f, e2p1 = 0.f, e2p2 = 0.f, e2p3 = 0.f;
#pragma unroll
    for (int k = 0; k < 4; ++k) {
        float v1 = 0.f, v2 = 0.f;
        if (k < nsteps) {
            const int ei = role ? (len - 1 - k) : (1 + k);
            const size_t eb = ((size_t)ei * B_N + b) * T_TAG;
            v1 = g_emis[eb + j1];
            v2 = has2 ? g_emis[eb + j2] : 0.f;
        }
        if (k == 0) { e1p0 = v1; e2p0 = v2; }
        else if (k == 1) { e1p1 = v1; e2p1 = v2; }
        else if (k == 2) { e1p2 = v1; e2p2 = v2; }
        else { e1p3 = v1; e2p3 = v2; }
    }

    for (int t = 0; t < nsteps; ++t) {
        // prefetch emission for t+4
        float ft1 = 0.f, ft2 = 0.f;
        if (t + 4 < nsteps) {
            const int ei = role ? (len - 5 - t) : (5 + t);
            const size_t eb = ((size_t)ei * B_N + b) * T_TAG;
            ft1 = g_emis[eb + j1];
            ft2 = has2 ? g_emis[eb + j2] : 0.f;
        }

        float x1, x2;
        if (role == 0) {
            x1 = p1;
            x2 = p2;
        } else {
            x1 = p1 * __expf(e1p0);
            x2 = has2 ? p2 * __expf(e2p0) : 0.f;
        }
        x_s[wid][j1] = x1;
        if (has2) x_s[wid][j2] = x2;
        __syncwarp();

        // matvec: j1 from register E row, j2 from smem
        ull A0 = 0ull, A1 = 0ull, B0 = 0ull, B1 = 0ull;
        const ulonglong2* px = (const ulonglong2*)x_s[wid];
#pragma unroll
        for (int i4 = 0; i4 < 12; ++i4) {
            ulonglong2 pv = px[i4];
            ffma2(A0, pv.x, e1r[2 * i4]);
            ffma2(A1, pv.y, e1r[2 * i4 + 1]);
            if (has2) {
                ulonglong2 mv2 = m2[i4];
                ffma2(B0, pv.x, mv2.x);
                ffma2(B1, pv.y, mv2.y);
            }
        }
        float2 a0 = unpack2(A0), a1 = unpack2(A1);
        float s1 = (a0.x + a0.y) + (a1.x + a1.y);
        float s2;
        {
            float2 b0v = unpack2(B0), b1v = unpack2(B1);
            s2 = (b0v.x + b0v.y) + (b1v.x + b1v.y);
        }

        if (role == 0) {
            p1 = s1 * __expf(e1p0);
            p2 = has2 ? s2 * __expf(e2p0) : 0.f;
        } else {
            p1 = s1;
            p2 = has2 ? s2 : 0.f;
        }
        // shift emission pipeline
        e1p0 = e1p1; e1p1 = e1p2; e1p2 = e1p3; e1p3 = ft1;
        e2p0 = e2p1; e2p1 = e2p2; e2p2 = e2p3; e2p3 = ft2;

        // renorm every 8 steps (growth/step <= ~1e4 -> 8 steps ~1e32 << fp32 max)
        if ((t & 7) == 7) {
            float S = warp_sum(p1 + p2);
            float inv = 1.f / S;
            p1 *= inv;
            p2 *= inv;
            logZ += __logf(S);
        }
        __syncwarp();
    }

    x_s[wid][j1] = p1;
    if (has2) x_s[wid][j2] = p2;
    if (lane == 0) lz_s[wid] = logZ;
    __syncthreads();

    if (role == 0) {
        float dsum = x_s[wid][j1] * x_s[wid + 1][j1];
        if (has2) dsum += x_s[wid][j2] * x_s[wid + 1][j2];
        dsum = warp_sum(dsum);
        if (lane == 0) {
            float denom = lz_s[wid] + lz_s[wid + 1] + __logf(dsum);
            g_llh[b] = (np_s[wid] + np_s[wid + 1]) - denom;
        }
    }

    // ---- fused final reduction: last CTA computes -mean(llh) ----
    __syncthreads();
    if (tid == 0) {
        __threadfence();
        int prev = atomicAdd(&g_crf_ctr, 1);
        last_s = (prev == (int)gridDim.x - 1) ? 1 : 0;
    }
    __syncthreads();
    if (last_s) {
        __shared__ float red[128];
        float v = g_llh[tid] + g_llh[tid + 128];
        red[tid] = v;
        __syncthreads();
        for (int s = 64; s > 0; s >>= 1) {
            if (tid < s) red[tid] += red[tid + s];
            __syncthreads();
        }
        if (tid == 0) {
            out[0] = -red[0] / (float)B_N;
            g_crf_ctr = 0;   // reset for next (deterministic) run
        }
    }
}

// ============================================================================
// launch
// ============================================================================
extern "C" void kernel_launch(void* const* d_in, const int* in_sizes, int n_in,
                              void* d_out, int out_size) {
    const int*   words  = (const int*)d_in[0];
    const int*   tags   = (const int*)d_in[1];
    // d_in[2] = mask (unused; derived from words != 0)
    const float* emb    = (const float*)d_in[3];
    const float* Wih_f  = (const float*)d_in[4];
    const float* Whh_f  = (const float*)d_in[5];
    const float* bih_f  = (const float*)d_in[6];
    const float* bhh_f  = (const float*)d_in[7];
    const float* Wih_b  = (const float*)d_in[8];
    const float* Whh_b  = (const float*)d_in[9];
    const float* bih_b  = (const float*)d_in[10];
    const float* bhh_b  = (const float*)d_in[11];
    const float* Wout   = (const float*)d_in[12];
    const float* bout   = (const float*)d_in[13];
    const float* trans  = (const float*)d_in[14];
    const float* st     = (const float*)d_in[15];
    const float* et     = (const float*)d_in[16];
    float* out = (float*)d_out;

    cudaFuncSetAttribute(xproj_mma_kernel, cudaFuncAttributeMaxDynamicSharedMemorySize,
                         XPM_SMEM);
    cudaFuncSetAttribute(lstm_mma_kernel, cudaFuncAttributeMaxDynamicSharedMemorySize,
                         LSTM_SMEM);
    cudaFuncSetAttribute(emis_mma_kernel, cudaFuncAttributeMaxDynamicSharedMemorySize,
                         EMM_SMEM);

    // 1) input projections via HMMA (bf16 output)
    xproj_mma_kernel<<<dim3(4, (L_SEQ * B_N) / 128, 2), 256, XPM_SMEM>>>(
        words, emb, Wih_f, bih_f, bhh_f, Wih_b, bih_b, bhh_b);

    // 2) HMMA BiLSTM: NB=4 -> 64 CTAs x 2 dirs = 128 CTAs (1/SM)
    lstm_mma_kernel<<<dim3(B_N / NB, 2), 256, LSTM_SMEM>>>(Whh_f, Whh_b);

    // 3) emissions via HMMA
    emis_mma_kernel<<<(L_SEQ * B_N) / 128, 256, EMM_SMEM>>>(Wout, bout);

    // 4) CRF: fwd/bwd split, reg-hoisted E row, renorm/8 (fused final reduction)
    crf_kernel<<<B_N / 2, 128>>>(words, tags, trans, st, et, out);
}

// round 15
// speedup vs baseline: 1.9176x; 1.4849x over previous
#include <cuda_runtime.h>
#include <cuda_fp16.h>
#include <cuda_bf16.h>
#include <cstdint>

// ---------------- problem constants ----------------
#define L_SEQ 512
#define B_N   256
#define E_DIM 128
#define H_DIM 128
#define G4    512     // 4*H
#define V_SZ  32000
#define T_TAG 48
#define NB    4       // batch lanes per LSTM CTA (half of mma N=8 tile)

typedef unsigned long long ull;

// ---------------- scratch (device globals; no allocation allowed) ----------------
__device__ __nv_bfloat16 g_xw[(size_t)V_SZ * 1024];            // 64 MiB [v][dir*512+g]
__device__ __nv_bfloat16 g_hcat[(size_t)L_SEQ * B_N * 256];    // 64 MiB [l][b][2H]
__device__ float g_emis[(size_t)L_SEQ * B_N * T_TAG];          // 24 MiB
__device__ float g_llh[B_N];
__device__ int   g_crf_ctr;                                    // zero-init; reset each run

// ---------------- generic helpers ----------------
__device__ __forceinline__ float tanh_fast(float x) {
    float y;
    asm("tanh.approx.f32 %0, %1;" : "=f"(y) : "f"(x));
    return y;
}
__device__ __forceinline__ float sig_fast(float x) {
    return fmaf(0.5f, tanh_fast(0.5f * x), 0.5f);
}
__device__ __forceinline__ uint32_t smem_u32(const void* p) {
    uint32_t a;
    asm("{ .reg .u64 t; cvta.to.shared.u64 t, %1; cvt.u32.u64 %0, t; }" : "=r"(a) : "l"(p));
    return a;
}
__device__ __forceinline__ uint32_t bf2(float x, float y) {
    __nv_bfloat162 t = __floats2bfloat162_rn(x, y);
    return *(uint32_t*)&t;
}
__device__ __forceinline__ void ffma2(ull& d, ull a, ull b) {
    asm("fma.rn.f32x2 %0, %1, %2, %0;" : "+l"(d) : "l"(a), "l"(b));
}
__device__ __forceinline__ float2 unpack2(ull v) {
    float2 r;
    asm("mov.b64 {%0, %1}, %2;" : "=f"(r.x), "=f"(r.y) : "l"(v));
    return r;
}
__device__ __forceinline__ void mma_bf16(float* d, const uint32_t* a, const uint32_t* b) {
    asm volatile(
        "mma.sync.aligned.m16n8k16.row.col.f32.bf16.bf16.f32 "
        "{%0,%1,%2,%3}, {%4,%5,%6,%7}, {%8,%9}, {%0,%1,%2,%3};"
        : "+f"(d[0]), "+f"(d[1]), "+f"(d[2]), "+f"(d[3])
        : "r"(a[0]), "r"(a[1]), "r"(a[2]), "r"(a[3]), "r"(b[0]), "r"(b[1]));
}
__device__ __forceinline__ void ldmatrix_x2_trans(uint32_t* r, uint32_t addr) {
    asm volatile("ldmatrix.sync.aligned.m8n8.x2.trans.shared.b16 {%0,%1}, [%2];"
                 : "=r"(r[0]), "=r"(r[1]) : "r"(addr));
}
__device__ __forceinline__ void ldsm_x4(uint32_t* r, uint32_t a) {
    asm volatile("ldmatrix.sync.aligned.m8n8.x4.shared.b16 {%0,%1,%2,%3}, [%4];"
                 : "=r"(r[0]), "=r"(r[1]), "=r"(r[2]), "=r"(r[3]) : "r"(a));
}
__device__ __forceinline__ void ldsm_x2(uint32_t* r, uint32_t a) {
    asm volatile("ldmatrix.sync.aligned.m8n8.x2.shared.b16 {%0,%1}, [%2];"
                 : "=r"(r[0]), "=r"(r[1]) : "r"(a));
}
__device__ __forceinline__ void cp16(uint32_t dst, const void* src) {
    asm volatile("cp.async.ca.shared.global [%0], [%1], 16;" :: "r"(dst), "l"(src));
}
__device__ __forceinline__ float warp_sum(float v) {
#pragma unroll
    for (int o = 16; o; o >>= 1) v += __shfl_xor_sync(0xFFFFFFFFu, v, o);
    return v;
}

// ============================================================================
// Kernel 1: xw[v][G] = emb[v] . Wih_{G>>9}[G&511] + bias  (vocab-level GEMM,
// 4x fewer FLOPs than per-token xproj; LSTM gathers rows from this table).
// M = 32000 (250 tiles of 128), N = 1024 (8 chunks of 128), K = 128.
// ============================================================================
#define XPM_A_OFF    0
#define XPM_B_OFF    (128 * 136 * 2)
#define XPM_BIAS_OFF (2 * 128 * 136 * 2)
#define XPM_SMEM     (XPM_BIAS_OFF + 128 * 4)

__global__ __launch_bounds__(256) void xw_mma_kernel(
    const float* __restrict__ emb,
    const float* __restrict__ Wih_f, const float* __restrict__ bih_f,
    const float* __restrict__ bhh_f, const float* __restrict__ Wih_b,
    const float* __restrict__ bih_b, const float* __restrict__ bhh_b) {
    extern __shared__ char xsm[];
    __nv_bfloat16* A_s = (__nv_bfloat16*)(xsm + XPM_A_OFF);   // [128][136]
    __nv_bfloat16* B_s = (__nv_bfloat16*)(xsm + XPM_B_OFF);   // [128][136]
    float* bias_s      = (float*)(xsm + XPM_BIAS_OFF);        // [128]

    const int row0 = blockIdx.y * 128;    // vocab row
    const int n0   = blockIdx.x * 128;    // concat gate G
    const int tid  = threadIdx.x;

    if (tid < 128) {
        const int G = n0 + tid;
        const int gr = G & 511;
        bias_s[tid] = (G >> 9) ? (bih_b[gr] + bhh_b[gr]) : (bih_f[gr] + bhh_f[gr]);
    }

    // A: emb rows (direct) -> bf16 [r][k], 136-elem row pad
    {
        const int r = tid >> 1, hf = tid & 1;
        const float4* src = (const float4*)(emb + (size_t)(row0 + r) * E_DIM + hf * 64);
        __nv_bfloat16* dst = A_s + r * 136 + hf * 64;
#pragma unroll
        for (int i = 0; i < 8; ++i) {
            float4 v0 = src[2 * i], v1 = src[2 * i + 1];
            uint4 pk;
            pk.x = bf2(v0.x, v0.y);
            pk.y = bf2(v0.z, v0.w);
            pk.z = bf2(v1.x, v1.y);
            pk.w = bf2(v1.z, v1.w);
            *(uint4*)(dst + i * 8) = pk;
        }
    }
    // B: concat [Wih_f; Wih_b] rows -> bf16 [n][k]
    {
        const int r = tid >> 1, hf = tid & 1;
        const int G = n0 + r;
        const float* W = (G >> 9) ? Wih_b : Wih_f;
        const float4* src = (const float4*)(W + (size_t)(G & 511) * E_DIM + hf * 64);
        __nv_bfloat16* dst = B_s + r * 136 + hf * 64;
#pragma unroll
        for (int i = 0; i < 8; ++i) {
            float4 v0 = src[2 * i], v1 = src[2 * i + 1];
            uint4 pk;
            pk.x = bf2(v0.x, v0.y);
            pk.y = bf2(v0.z, v0.w);
            pk.z = bf2(v1.x, v1.y);
            pk.w = bf2(v1.z, v1.w);
            *(uint4*)(dst + i * 8) = pk;
        }
    }
    __syncthreads();

    const uint32_t As = smem_u32(A_s), Bs = smem_u32(B_s);
    const int lane = tid & 31, wid = tid >> 5;
    const int m_base = (wid >> 1) * 32;
    const int n_base = (wid & 1) * 64;

    float d[2][8][4];
#pragma unroll
    for (int mt = 0; mt < 2; ++mt)
#pragma unroll
        for (int nt = 0; nt < 8; ++nt)
#pragma unroll
            for (int c = 0; c < 4; ++c) d[mt][nt][c] = 0.f;

    const int aq = lane >> 3;
    const uint32_t a_row = (uint32_t)((aq & 1) * 8 + (lane & 7));
    const uint32_t a_col = (uint32_t)((aq >> 1) * 16);
    const uint32_t b_row = (uint32_t)(lane & 7);
    const uint32_t b_col = (uint32_t)(((lane >> 3) & 1) * 16);

#pragma unroll
    for (int ks = 0; ks < 8; ++ks) {
        uint32_t a0[4], a1[4];
        ldsm_x4(a0, As + (m_base + 0 + a_row) * 272 + ks * 32 + a_col);
        ldsm_x4(a1, As + (m_base + 16 + a_row) * 272 + ks * 32 + a_col);
#pragma unroll
        for (int nt = 0; nt < 8; ++nt) {
            uint32_t bb[2];
            ldsm_x2(bb, Bs + (n_base + nt * 8 + b_row) * 272 + ks * 32 + b_col);
            mma_bf16(d[0][nt], a0, bb);
            mma_bf16(d[1][nt], a1, bb);
        }
    }

    const int r = lane >> 2, c = (lane & 3) * 2;
#pragma unroll
    for (int mt = 0; mt < 2; ++mt) {
        const int gr = row0 + m_base + mt * 16 + r;
#pragma unroll
        for (int nt = 0; nt < 8; ++nt) {
            const int gc = n_base + nt * 8 + c;
            const float bx = bias_s[gc], by = bias_s[gc + 1];
            *(uint32_t*)(g_xw + (size_t)gr * 1024 + n0 + gc) =
                bf2(d[mt][nt][0] + bx, d[mt][nt][1] + by);
            *(uint32_t*)(g_xw + (size_t)(gr + 8) * 1024 + n0 + gc) =
                bf2(d[mt][nt][2] + bx, d[mt][nt][3] + by);
        }
    }
}

// ============================================================================
// Kernel 2: HMMA LSTM (R14 form), x gathered from g_xw[word] via cp.async.
// 256 threads, NB=4 batch/CTA (128 CTAs -> 1/SM), 4-buffer staging.
// ============================================================================
#define LSTM_HBUF   0
#define LSTM_XBUF   4096
#define XB_STRIDE   520                       // bf16 units per batch row
#define XB_BUFSZ    (4 * XB_STRIDE)           // bf16 units per buffer
#define LSTM_WOFF   (4096 + 4 * XB_BUFSZ * 2)
#define LSTM_SMEM   (LSTM_WOFF + 4 * L_SEQ * 4)

__global__ __launch_bounds__(256) void lstm_mma_kernel(const float* __restrict__ Whh_f,
                                                       const float* __restrict__ Whh_b,
                                                       const int* __restrict__ words) {
    extern __shared__ char smraw[];
    uint32_t* hbuf      = (uint32_t*)(smraw + LSTM_HBUF);       // [2][128][4 bf16x2]
    __nv_bfloat16* xbuf = (__nv_bfloat16*)(smraw + LSTM_XBUF);  // [4][4][520]
    int* w_s            = (int*)(smraw + LSTM_WOFF);            // [4][512]

    const int tid  = threadIdx.x;
    const int lane = tid & 31;
    const int wid  = tid >> 5;
    const int gid  = lane >> 2;
    const int tig  = lane & 3;
    const int dir  = blockIdx.y;
    const int b0   = blockIdx.x * NB;
    const float* Whh = dir ? Whh_b : Whh_f;
    __nv_bfloat16* hout = g_hcat + dir * 128;

    const uint32_t hb_u32 = smem_u32(hbuf);
    const uint32_t xb_u32 = smem_u32(xbuf);
    const bool live = (tig < 2);   // batches 2*tig, 2*tig+1 in [0,4)

    // word indices for the 4 batch rows (contiguous 2048 ints)
    {
        const int4* wsrc = (const int4*)(words + (size_t)b0 * L_SEQ);
        for (int i = tid; i < 512; i += 256) ((int4*)w_s)[i] = wsrc[i];
    }

    uint32_t afr[4][8][4];
#pragma unroll
    for (int q = 0; q < 4; ++q) {
        const int r0 = 16 * wid + 128 * q + gid;
#pragma unroll
        for (int ks = 0; ks < 8; ++ks) {
            const int cc = ks * 16 + 2 * tig;
            float2 v00 = *(const float2*)(Whh + (size_t)r0 * 128 + cc);
            float2 v10 = *(const float2*)(Whh + (size_t)(r0 + 8) * 128 + cc);
            float2 v01 = *(const float2*)(Whh + (size_t)r0 * 128 + cc + 8);
            float2 v11 = *(const float2*)(Whh + (size_t)(r0 + 8) * 128 + cc + 8);
            afr[q][ks][0] = bf2(v00.x, v00.y);
            afr[q][ks][1] = bf2(v10.x, v10.y);
            afr[q][ks][2] = bf2(v01.x, v01.y);
            afr[q][ks][3] = bf2(v11.x, v11.y);
        }
    }

    for (int i = tid; i < 2 * 128 * 4; i += 256) hbuf[i] = 0;
    __syncthreads();   // w_s + hbuf ready

    // prologue: prefetch x(0..2) — 256 x 16B per buffer (1 cp16/thread)
#pragma unroll
    for (int ps = 0; ps < 3; ++ps) {
        const int l = dir ? (L_SEQ - 1 - ps) : ps;
        const int brow = tid >> 6, c16 = tid & 63;
        const int w = w_s[brow * L_SEQ + l];
        cp16(xb_u32 + (uint32_t)(ps * XB_BUFSZ * 2 + brow * XB_STRIDE * 2 + c16 * 16),
             g_xw + (size_t)w * 1024 + dir * 512 + c16 * 8);
        asm volatile("cp.async.commit_group;");
    }
    asm volatile("cp.async.wait_group 2;");   // x(0) ready
    __syncthreads();

    float cst[4] = {0.f, 0.f, 0.f, 0.f};

    for (int s = 0; s < L_SEQ; ++s) {
        const int l = dir ? (L_SEQ - 1 - s) : s;

        // issue prefetch x(s+3) (group always committed to keep the count)
        if (s + 3 < L_SEQ) {
            const int lf = dir ? (L_SEQ - 4 - s) : (s + 3);
            const uint32_t dbase = xb_u32 + (uint32_t)(((s + 3) & 3) * XB_BUFSZ * 2);
            const int brow = tid >> 6, c16 = tid & 63;
            const int w = w_s[brow * L_SEQ + lf];
            cp16(dbase + (uint32_t)(brow * XB_STRIDE * 2 + c16 * 16),
                 g_xw + (size_t)w * 1024 + dir * 512 + c16 * 8);
        }
        asm volatile("cp.async.commit_group;");

        uint32_t rb[8][2];
        const uint32_t base = hb_u32 + (uint32_t)((s & 1) * 2048) + ((uint32_t)(lane & 15) << 4);
#pragma unroll
        for (int ks = 0; ks < 8; ++ks) ldmatrix_x2_trans(rb[ks], base + ks * 256);

        float d[4][4];
#pragma unroll
        for (int q = 0; q < 4; ++q)
#pragma unroll
            for (int c = 0; c < 4; ++c) d[q][c] = 0.f;
#pragma unroll
        for (int ks = 0; ks < 8; ++ks)
#pragma unroll
            for (int q = 0; q < 4; ++q) mma_bf16(d[q], afr[q][ks], rb[ks]);

        // activations (live lanes carry real batches; dead lanes bounded garbage)
        const __nv_bfloat16* xb_base = xbuf + (s & 3) * XB_BUFSZ;
        float hv[4];
#pragma unroll
        for (int p = 0; p < 4; ++p) {
            const int br = (2 * tig + (p & 1)) & 3;
            const __nv_bfloat16* xr = xb_base + br * XB_STRIDE + 16 * wid + gid + 8 * (p >> 1);
            float gi = d[0][p] + __bfloat162float(xr[0]);
            float gf = d[1][p] + __bfloat162float(xr[128]);
            float gg = d[2][p] + __bfloat162float(xr[256]);
            float go = d[3][p] + __bfloat162float(xr[384]);
            float cn = sig_fast(gf) * cst[p] + sig_fast(gi) * tanh_fast(gg);
            cst[p] = cn;
            hv[p] = sig_fast(go) * tanh_fast(cn);
        }

        if (live) {
            const int r0 = 16 * wid + gid;
            hbuf[((s + 1) & 1) * 512 + r0 * 4 + tig]       = bf2(hv[0], hv[1]);
            hbuf[((s + 1) & 1) * 512 + (r0 + 8) * 4 + tig] = bf2(hv[2], hv[3]);

            const size_t orow = ((size_t)l * B_N + b0 + 2 * tig) * 256;
            hout[orow + r0]           = __float2bfloat16(hv[0]);
            hout[orow + 256 + r0]     = __float2bfloat16(hv[1]);
            hout[orow + r0 + 8]       = __float2bfloat16(hv[2]);
            hout[orow + 256 + r0 + 8] = __float2bfloat16(hv[3]);
        }

        asm volatile("cp.async.wait_group 2;");   // x(s+1) ready
        __syncthreads();
    }
}

// ============================================================================
// Kernel 3: emis via HMMA. M=128 rows, N=48 tags, K=256. (unchanged)
// ============================================================================
#define EMM_A_OFF    0
#define EMM_B_OFF    (128 * 264 * 2)
#define EMM_BIAS_OFF (EMM_B_OFF + 48 * 264 * 2)
#define EMM_SMEM     (EMM_BIAS_OFF + 48 * 4)

__global__ __launch_bounds__(256) void emis_mma_kernel(const float* __restrict__ Wout,
                                                       const float* __restrict__ bout) {
    extern __shared__ char esm[];
    __nv_bfloat16* A_s = (__nv_bfloat16*)(esm + EMM_A_OFF);   // [128][264]
    __nv_bfloat16* B_s = (__nv_bfloat16*)(esm + EMM_B_OFF);   // [48][264]
    float* bias_s      = (float*)(esm + EMM_BIAS_OFF);        // [48]

    const int tid = threadIdx.x;
    const int row0 = blockIdx.x * 128;

    if (tid < 48) bias_s[tid] = bout[tid];

    {
        const int r = tid >> 1, hf = tid & 1;
        const uint4* src = (const uint4*)(g_hcat + (size_t)(row0 + r) * 256 + hf * 128);
        uint4* dst = (uint4*)(A_s + r * 264 + hf * 128);
#pragma unroll
        for (int i = 0; i < 16; ++i) dst[i] = src[i];
    }
    if (tid < 96) {
        const int r = tid >> 1, hf = tid & 1;
        const float4* src = (const float4*)(Wout + (size_t)r * 256 + hf * 128);
        __nv_bfloat16* dst = B_s + r * 264 + hf * 128;
#pragma unroll
        for (int i = 0; i < 16; ++i) {
            float4 v0 = src[2 * i], v1 = src[2 * i + 1];
            uint4 pk;
            pk.x = bf2(v0.x, v0.y);
            pk.y = bf2(v0.z, v0.w);
            pk.z = bf2(v1.x, v1.y);
            pk.w = bf2(v1.z, v1.w);
            *(uint4*)(dst + i * 8) = pk;
        }
    }
    __syncthreads();

    const uint32_t As = smem_u32(A_s), Bs = smem_u32(B_s);
    const int lane = tid & 31, wid = tid >> 5;
    const int m_base = (wid >> 1) * 32;
    const int n_base = (wid & 1) * 24;

    const int aq = lane >> 3;
    const uint32_t a_row = (uint32_t)((aq & 1) * 8 + (lane & 7));
    const uint32_t a_col = (uint32_t)((aq >> 1) * 16);
    const uint32_t b_row = (uint32_t)(lane & 7);
    const uint32_t b_col = (uint32_t)(((lane >> 3) & 1) * 16);

    float d[2][3][4];
#pragma unroll
    for (int mt = 0; mt < 2; ++mt)
#pragma unroll
        for (int nt = 0; nt < 3; ++nt)
#pragma unroll
            for (int c = 0; c < 4; ++c) d[mt][nt][c] = 0.f;

#pragma unroll
    for (int ks = 0; ks < 16; ++ks) {
        uint32_t a0[4], a1[4];
        ldsm_x4(a0, As + (m_base + 0 + a_row) * 528 + ks * 32 + a_col);
        ldsm_x4(a1, As + (m_base + 16 + a_row) * 528 + ks * 32 + a_col);
#pragma unroll
        for (int nt = 0; nt < 3; ++nt) {
            uint32_t bb[2];
            ldsm_x2(bb, Bs + (n_base + nt * 8 + b_row) * 528 + ks * 32 + b_col);
            mma_bf16(d[0][nt], a0, bb);
            mma_bf16(d[1][nt], a1, bb);
        }
    }

    const int r = lane >> 2, c = (lane & 3) * 2;
#pragma unroll
    for (int mt = 0; mt < 2; ++mt) {
        const int gr = row0 + m_base + mt * 16 + r;
#pragma unroll
        for (int nt = 0; nt < 3; ++nt) {
            const int gc = n_base + nt * 8 + c;
            const float bx = bias_s[gc], by = bias_s[gc + 1];
            float2 o0 = make_float2(d[mt][nt][0] + bx, d[mt][nt][1] + by);
            float2 o1 = make_float2(d[mt][nt][2] + bx, d[mt][nt][3] + by);
            *(float2*)(g_emis + (size_t)gr * T_TAG + gc) = o0;
            *(float2*)(g_emis + (size_t)(gr + 8) * T_TAG + gc) = o1;
        }
    }
}

// ============================================================================
// Kernel 4: CRF (R14 form: fwd/bwd split, reg-hoisted E row, renorm/8,
// fused final reduction).
// ============================================================================
__global__ __launch_bounds__(128, 1) void crf_kernel(const int* __restrict__ words,
                                                     const int* __restrict__ tags,
                                                     const float* __restrict__ trans,
                                                     const float* __restrict__ start_trans,
                                                     const float* __restrict__ end_trans,
                                                     float* __restrict__ out) {
    __shared__ __align__(16) float Efw_s[48 * 52];
    __shared__ __align__(16) float Ebw_s[48 * 52];
    __shared__ __align__(16) float tr_s[48 * 48];
    __shared__ __align__(16) float x_s[4][48];
    __shared__ float lz_s[4];
    __shared__ float np_s[4];
    __shared__ int last_s;

    const int tid = threadIdx.x;
    const int wid = tid >> 5, lane = tid & 31;
    const int role = wid & 1;            // 0 = forward, 1 = backward
    const int b = blockIdx.x * 2 + (wid >> 1);

    for (int idx = tid; idx < 48 * 48; idx += 128) {
        float v = trans[idx];
        tr_s[idx] = v;
        float e = __expf(v);
        const int i = idx / 48, j = idx - i * 48;
        Efw_s[j * 52 + i] = e;
        Ebw_s[i * 52 + j] = e;
    }
    __syncthreads();

    // sequence length (prefix mask == words != 0)
    int cnt = 0;
    for (int l = lane; l < L_SEQ; l += 32) cnt += (words[b * L_SEQ + l] != 0) ? 1 : 0;
#pragma unroll
    for (int o = 16; o; o >>= 1) cnt += __shfl_xor_sync(0xFFFFFFFFu, cnt, o);
    const int len = cnt;
    const int c = len >> 1;

    const int j1 = lane;
    const int j2 = 32 + lane;
    const bool has2 = lane < 16;

    // hoist this lane's own E row (j1) into registers: 24 ull = 48 floats
    ull e1r[24];
    {
        const ull* src = (const ull*)((role ? Ebw_s : Efw_s) + j1 * 52);
#pragma unroll
        for (int i = 0; i < 24; ++i) e1r[i] = src[i];
    }
    const ulonglong2* m2 = (const ulonglong2*)((role ? Ebw_s : Efw_s) + j2 * 52);

    // ---- numerator partial ----
    {
        const int lo = role ? (c + 1) : 1;
        const int hi = role ? len : (c + 1);
        float np = 0.f;
        for (int l = lo + lane; l < hi; l += 32) {
            int tp = tags[b * L_SEQ + l - 1];
            int tc = tags[b * L_SEQ + l];
            np += tr_s[tp * 48 + tc] + g_emis[((size_t)l * B_N + b) * T_TAG + tc];
        }
        np = warp_sum(np);
        if (lane == 0) {
            if (role == 0) {
                int t0 = tags[b * L_SEQ];
                np += start_trans[t0] + g_emis[(size_t)b * T_TAG + t0];
            } else {
                np += end_trans[tags[b * L_SEQ + (len - 1)]];
            }
            np_s[wid] = np;
        }
    }

    // ---- init vector ----
    float p1, p2, logZ = 0.f;
    if (role == 0) {
        p1 = __expf(start_trans[j1] + g_emis[(size_t)b * T_TAG + j1]);
        p2 = has2 ? __expf(start_trans[j2] + g_emis[(size_t)b * T_TAG + j2]) : 0.f;
    } else {
        p1 = __expf(end_trans[j1]);
        p2 = has2 ? __expf(end_trans[j2]) : 0.f;
    }

    const int nsteps = role ? (len - 1 - c) : c;

    // emission position for step t: fwd -> 1+t, bwd -> len-1-t.  4-deep pipeline.
    float e1p0 = 0.f, e1p1 = 0.f, e1p2 = 0.f, e1p3 = 0.f;
    float e2p0 = 0.f, e2p1 = 0.f, e2p2 = 0.f, e2p3 = 0.f;
#pragma unroll
    for (int k = 0; k < 4; ++k) {
        float v1 = 0.f, v2 = 0.f;
        if (k < nsteps) {
            const int ei = role ? (len - 1 - k) : (1 + k);
            const size_t eb = ((size_t)ei * B_N + b) * T_TAG;
            v1 = g_emis[eb + j1];
            v2 = has2 ? g_emis[eb + j2] : 0.f;
        }
        if (k == 0) { e1p0 = v1; e2p0 = v2; }
        else if (k == 1) { e1p1 = v1; e2p1 = v2; }
        else if (k == 2) { e1p2 = v1; e2p2 = v2; }
        else { e1p3 = v1; e2p3 = v2; }
    }

    for (int t = 0; t < nsteps; ++t) {
        // prefetch emission for t+4
        float ft1 = 0.f, ft2 = 0.f;
        if (t + 4 < nsteps) {
            const int ei = role ? (len - 5 - t) : (5 + t);
            const size_t eb = ((size_t)ei * B_N + b) * T_TAG;
            ft1 = g_emis[eb + j1];
            ft2 = has2 ? g_emis[eb + j2] : 0.f;
        }

        float x1, x2;
        if (role == 0) {
            x1 = p1;
            x2 = p2;
        } else {
            x1 = p1 * __expf(e1p0);
            x2 = has2 ? p2 * __expf(e2p0) : 0.f;
        }
        x_s[wid][j1] = x1;
        if (has2) x_s[wid][j2] = x2;
        __syncwarp();

        // matvec: j1 from register E row, j2 from smem
        ull A0 = 0ull, A1 = 0ull, B0 = 0ull, B1 = 0ull;
        const ulonglong2* px = (const ulonglong2*)x_s[wid];
#pragma unroll
        for (int i4 = 0; i4 < 12; ++i4) {
            ulonglong2 pv = px[i4];
            ffma2(A0, pv.x, e1r[2 * i4]);
            ffma2(A1, pv.y, e1r[2 * i4 + 1]);
            if (has2) {
                ulonglong2 mv2 = m2[i4];
                ffma2(B0, pv.x, mv2.x);
                ffma2(B1, pv.y, mv2.y);
            }
        }
        float2 a0 = unpack2(A0), a1 = unpack2(A1);
        float s1 = (a0.x + a0.y) + (a1.x + a1.y);
        float s2;
        {
            float2 b0v = unpack2(B0), b1v = unpack2(B1);
            s2 = (b0v.x + b0v.y) + (b1v.x + b1v.y);
        }

        if (role == 0) {
            p1 = s1 * __expf(e1p0);
            p2 = has2 ? s2 * __expf(e2p0) : 0.f;
        } else {
            p1 = s1;
            p2 = has2 ? s2 : 0.f;
        }
        // shift emission pipeline
        e1p0 = e1p1; e1p1 = e1p2; e1p2 = e1p3; e1p3 = ft1;
        e2p0 = e2p1; e2p1 = e2p2; e2p2 = e2p3; e2p3 = ft2;

        // renorm every 8 steps (growth/step <= ~1e4 -> 8 steps ~1e32 << fp32 max)
        if ((t & 7) == 7) {
            float S = warp_sum(p1 + p2);
            float inv = 1.f / S;
            p1 *= inv;
            p2 *= inv;
            logZ += __logf(S);
        }
        __syncwarp();
    }

    x_s[wid][j1] = p1;
    if (has2) x_s[wid][j2] = p2;
    if (lane == 0) lz_s[wid] = logZ;
    __syncthreads();

    if (role == 0) {
        float dsum = x_s[wid][j1] * x_s[wid + 1][j1];
        if (has2) dsum += x_s[wid][j2] * x_s[wid + 1][j2];
        dsum = warp_sum(dsum);
        if (lane == 0) {
            float denom = lz_s[wid] + lz_s[wid + 1] + __logf(dsum);
            g_llh[b] = (np_s[wid] + np_s[wid + 1]) - denom;
        }
    }

    // ---- fused final reduction: last CTA computes -mean(llh) ----
    __syncthreads();
    if (tid == 0) {
        __threadfence();
        int prev = atomicAdd(&g_crf_ctr, 1);
        last_s = (prev == (int)gridDim.x - 1) ? 1 : 0;
    }
    __syncthreads();
    if (last_s) {
        __shared__ float red[128];
        float v = g_llh[tid] + g_llh[tid + 128];
        red[tid] = v;
        __syncthreads();
        for (int s = 64; s > 0; s >>= 1) {
            if (tid < s) red[tid] += red[tid + s];
            __syncthreads();
        }
        if (tid == 0) {
            out[0] = -red[0] / (float)B_N;
            g_crf_ctr = 0;   // reset for next (deterministic) run
        }
    }
}

// ============================================================================
// launch
// ============================================================================
extern "C" void kernel_launch(void* const* d_in, const int* in_sizes, int n_in,
                              void* d_out, int out_size) {
    const int*   words  = (const int*)d_in[0];
    const int*   tags   = (const int*)d_in[1];
    // d_in[2] = mask (unused; derived from words != 0)
    const float* emb    = (const float*)d_in[3];
    const float* Wih_f  = (const float*)d_in[4];
    const float* Whh_f  = (const float*)d_in[5];
    const float* bih_f  = (const float*)d_in[6];
    const float* bhh_f  = (const float*)d_in[7];
    const float* Wih_b  = (const float*)d_in[8];
    const float* Whh_b  = (const float*)d_in[9];
    const float* bih_b  = (const float*)d_in[10];
    const float* bhh_b  = (const float*)d_in[11];
    const float* Wout   = (const float*)d_in[12];
    const float* bout   = (const float*)d_in[13];
    const float* trans  = (const float*)d_in[14];
    const float* st     = (const float*)d_in[15];
    const float* et     = (const float*)d_in[16];
    float* out = (float*)d_out;

    cudaFuncSetAttribute(xw_mma_kernel, cudaFuncAttributeMaxDynamicSharedMemorySize,
                         XPM_SMEM);
    cudaFuncSetAttribute(lstm_mma_kernel, cudaFuncAttributeMaxDynamicSharedMemorySize,
                         LSTM_SMEM);
    cudaFuncSetAttribute(emis_mma_kernel, cudaFuncAttributeMaxDynamicSharedMemorySize,
                         EMM_SMEM);

    // 1) vocab-level input projection table: xw[v] = emb[v] @ [Wih_f|Wih_b]^T + bias
    xw_mma_kernel<<<dim3(8, V_SZ / 128), 256, XPM_SMEM>>>(
        emb, Wih_f, bih_f, bhh_f, Wih_b, bih_b, bhh_b);

    // 2) HMMA BiLSTM gathering x rows from g_xw: 64 CTAs x 2 dirs = 128 (1/SM)
    lstm_mma_kernel<<<dim3(B_N / NB, 2), 256, LSTM_SMEM>>>(Whh_f, Whh_b, words);

    // 3) emissions via HMMA
    emis_mma_kernel<<<(L_SEQ * B_N) / 128, 256, EMM_SMEM>>>(Wout, bout);

    // 4) CRF (fused final reduction)
    crf_kernel<<<B_N / 2, 128>>>(words, tags, trans, st, et, out);
}